// round 3
// baseline (speedup 1.0000x reference)
#include <cuda_runtime.h>
#include <cstdint>
#include <cstddef>

// Problem constants (match reference)
#define NMAX 100000
#define EMAX 1600000
#define K_DIM 128

// ---- Scratch (device globals; no allocations allowed) ----
__device__ int   g_deg[NMAX];
__device__ int   g_rowptr[NMAX + 1];
__device__ int   g_fill[NMAX];
__device__ int   g_col[EMAX];
__device__ float g_xl[(size_t)NMAX * 128];   // aggregated-path transform
__device__ float g_xr[(size_t)NMAX * 128];   // self-path transform (+bias)
__device__ float g_h[(size_t)NMAX * 128];    // layer-0 output
__device__ float g_h2[(size_t)NMAX * 128];   // layer-1 output

// ============================================================
// CSR build (counting sort by dst), rebuilt every launch
// ============================================================
__global__ void hist_k(const int* __restrict__ dst, int e) {
    int i = blockIdx.x * blockDim.x + threadIdx.x;
    if (i < e) atomicAdd(&g_deg[dst[i]], 1);
}

__global__ __launch_bounds__(1024) void scan_k(int n) {
    __shared__ int part[1024];
    int tid = threadIdx.x;
    int chunk = (n + 1023) >> 10;
    int beg = tid * chunk;
    int end = min(beg + chunk, n);
    int s = 0;
    for (int i = beg; i < end; i++) s += g_deg[i];
    part[tid] = s;
    __syncthreads();
    for (int off = 1; off < 1024; off <<= 1) {
        int v = (tid >= off) ? part[tid - off] : 0;
        __syncthreads();
        part[tid] += v;
        __syncthreads();
    }
    int base = part[tid] - s;  // exclusive prefix
    for (int i = beg; i < end; i++) {
        g_rowptr[i] = base;
        g_fill[i]   = base;
        base += g_deg[i];
    }
    if (tid == 1023) g_rowptr[n] = part[1023];
}

__global__ void scatter_k(const int* __restrict__ src, const int* __restrict__ dst, int e) {
    int i = blockIdx.x * blockDim.x + threadIdx.x;
    if (i < e) {
        int p = atomicAdd(&g_fill[dst[i]], 1);
        g_col[p] = src[i];
    }
}

// ============================================================
// tf32 helpers
// ============================================================
__device__ __forceinline__ uint32_t f2tf(float x) {
    uint32_t u;
    asm("cvt.rna.tf32.f32 %0, %1;" : "=r"(u) : "f"(x));
    return u;
}

__device__ __forceinline__ void mma_tf32(
    float c[4], uint32_t a0, uint32_t a1, uint32_t a2, uint32_t a3,
    uint32_t b0, uint32_t b1)
{
    asm volatile(
        "mma.sync.aligned.m16n8k8.row.col.f32.tf32.tf32.f32 "
        "{%0,%1,%2,%3}, {%4,%5,%6,%7}, {%8,%9}, {%0,%1,%2,%3};"
        : "+f"(c[0]), "+f"(c[1]), "+f"(c[2]), "+f"(c[3])
        : "r"(a0), "r"(a1), "r"(a2), "r"(a3), "r"(b0), "r"(b1));
}

// ============================================================
// Full-K GEMM (tf32 tensor cores):
//   C = A @ W (+bias)   blockIdx.y: 0 -> (Wl, Cl), 1 -> (Wr+bias, Cr)
// A: [n,128] row-major, W: [128,DOUT] row-major.
// BM=64 rows/block; whole K=128 staged once in smem; 1 sync total.
// 8 warps: warp = (rowgrp 0..3) x (n-half 0..1).
// ============================================================
template <int DOUT>
__global__ __launch_bounds__(256) void gemm_fullk(
    const float* __restrict__ A,
    const float* __restrict__ Wl, const float* __restrict__ Wr,
    const float* __restrict__ bias,
    float* __restrict__ Cl, float* __restrict__ Cr, int n)
{
    constexpr int BM = 64;
    constexpr int AS_STRIDE = K_DIM + 4;   // 132
    constexpr int BS_STRIDE = DOUT + 4;
    constexpr int NF = DOUT / 16;          // n-frags per warp (half of DOUT, /8)

    extern __shared__ uint32_t smraw[];
    uint32_t (*As)[AS_STRIDE] = (uint32_t(*)[AS_STRIDE])smraw;                    // [64][132]
    uint32_t (*Bs)[BS_STRIDE] = (uint32_t(*)[BS_STRIDE])(smraw + BM * AS_STRIDE); // [128][DOUT+4]

    const float* W = blockIdx.y ? Wr : Wl;
    float*       C = blockIdx.y ? Cr : Cl;
    const bool use_bias = (blockIdx.y == 1);

    const int tid  = threadIdx.x;
    const int row0 = blockIdx.x * BM;

    // ---- stage A: BM x 128 (8 float4/thread) ----
#pragma unroll
    for (int v = 0; v < (BM * K_DIM) / (4 * 256); v++) {
        int idx = tid + v * 256;
        int r   = idx >> 5;              // row 0..63
        int kq  = (idx & 31) * 4;        // k offset
        float4 av = make_float4(0.f, 0.f, 0.f, 0.f);
        int gr = row0 + r;
        if (gr < n) av = *(const float4*)(A + (size_t)gr * K_DIM + kq);
        uint4 uv;
        uv.x = f2tf(av.x); uv.y = f2tf(av.y);
        uv.z = f2tf(av.z); uv.w = f2tf(av.w);
        *(uint4*)&As[r][kq] = uv;
    }
    // ---- stage W: 128 x DOUT ----
#pragma unroll
    for (int v = 0; v < (K_DIM * DOUT) / (4 * 256); v++) {
        int idx = tid + v * 256;
        int kk  = idx / (DOUT / 4);
        int c4  = (idx % (DOUT / 4)) * 4;
        float4 bv = *(const float4*)(W + (size_t)kk * DOUT + c4);
        uint4 uv;
        uv.x = f2tf(bv.x); uv.y = f2tf(bv.y);
        uv.z = f2tf(bv.z); uv.w = f2tf(bv.w);
        *(uint4*)&Bs[kk][c4] = uv;
    }
    __syncthreads();

    const int warp  = tid >> 5;
    const int lane  = tid & 31;
    const int g     = lane >> 2;
    const int tig   = lane & 3;
    const int rgrp  = warp & 3;          // row group (x16)
    const int nh    = warp >> 2;         // n half
    const int wrow  = rgrp * 16;
    const int col0  = nh * (DOUT / 2);

    float acc[NF][4];
#pragma unroll
    for (int f = 0; f < NF; f++)
#pragma unroll
        for (int j = 0; j < 4; j++) acc[f][j] = 0.f;

#pragma unroll
    for (int kstep = 0; kstep < K_DIM / 8; kstep++) {
        const int kb = kstep * 8;
        uint32_t a0 = As[wrow + g][kb + tig];
        uint32_t a1 = As[wrow + g + 8][kb + tig];
        uint32_t a2 = As[wrow + g][kb + tig + 4];
        uint32_t a3 = As[wrow + g + 8][kb + tig + 4];
#pragma unroll
        for (int f = 0; f < NF; f++) {
            int col = col0 + f * 8 + g;
            uint32_t b0 = Bs[kb + tig][col];
            uint32_t b1 = Bs[kb + tig + 4][col];
            mma_tf32(acc[f], a0, a1, a2, a3, b0, b1);
        }
    }

    // ---- epilogue ----
    const int r_lo = row0 + wrow + g;
    const int r_hi = r_lo + 8;
#pragma unroll
    for (int f = 0; f < NF; f++) {
        int col = col0 + f * 8 + 2 * tig;
        float bv0 = use_bias ? bias[col]     : 0.f;
        float bv1 = use_bias ? bias[col + 1] : 0.f;
        if (r_lo < n) {
            float2 o = make_float2(acc[f][0] + bv0, acc[f][1] + bv1);
            *(float2*)(C + (size_t)r_lo * DOUT + col) = o;
        }
        if (r_hi < n) {
            float2 o = make_float2(acc[f][2] + bv0, acc[f][3] + bv1);
            *(float2*)(C + (size_t)r_hi * DOUT + col) = o;
        }
    }
}

// ============================================================
// Aggregation + epilogue: out[n] = relu?( mean_{s in N(n)} xl[s] + xr[n] )
// One warp per destination node. Neighbor indices fetched once per
// 32-edge chunk (coalesced), broadcast via shfl; 8 gathers in flight.
// ============================================================
template <int DOUT, bool RELU>
__global__ __launch_bounds__(256) void agg_ep(
    const float* __restrict__ xl, const float* __restrict__ xr,
    float* __restrict__ out, int n)
{
    int gw   = (blockIdx.x * blockDim.x + threadIdx.x) >> 5;
    int lane = threadIdx.x & 31;
    if (gw >= n) return;

    int beg = g_rowptr[gw];
    int end = g_rowptr[gw + 1];
    float inv = 1.f / fmaxf((float)(end - beg), 1.f);

    if (DOUT == 128) {
        const float4* X = (const float4*)xl;
        float4 a0 = {0,0,0,0}, a1 = {0,0,0,0}, a2 = {0,0,0,0}, a3 = {0,0,0,0};
        for (int base = beg; base < end; base += 32) {
            int m = end - base; if (m > 32) m = 32;
            int p = base + lane; if (p >= end) p = end - 1;
            int idx = g_col[p];
            int j = 0;
            for (; j + 8 <= m; j += 8) {
                int s0 = __shfl_sync(0xffffffffu, idx, j + 0);
                int s1 = __shfl_sync(0xffffffffu, idx, j + 1);
                int s2 = __shfl_sync(0xffffffffu, idx, j + 2);
                int s3 = __shfl_sync(0xffffffffu, idx, j + 3);
                int s4 = __shfl_sync(0xffffffffu, idx, j + 4);
                int s5 = __shfl_sync(0xffffffffu, idx, j + 5);
                int s6 = __shfl_sync(0xffffffffu, idx, j + 6);
                int s7 = __shfl_sync(0xffffffffu, idx, j + 7);
                float4 v0 = X[s0 * 32 + lane];
                float4 v1 = X[s1 * 32 + lane];
                float4 v2 = X[s2 * 32 + lane];
                float4 v3 = X[s3 * 32 + lane];
                float4 v4 = X[s4 * 32 + lane];
                float4 v5 = X[s5 * 32 + lane];
                float4 v6 = X[s6 * 32 + lane];
                float4 v7 = X[s7 * 32 + lane];
                a0.x += v0.x; a0.y += v0.y; a0.z += v0.z; a0.w += v0.w;
                a1.x += v1.x; a1.y += v1.y; a1.z += v1.z; a1.w += v1.w;
                a2.x += v2.x; a2.y += v2.y; a2.z += v2.z; a2.w += v2.w;
                a3.x += v3.x; a3.y += v3.y; a3.z += v3.z; a3.w += v3.w;
                a0.x += v4.x; a0.y += v4.y; a0.z += v4.z; a0.w += v4.w;
                a1.x += v5.x; a1.y += v5.y; a1.z += v5.z; a1.w += v5.w;
                a2.x += v6.x; a2.y += v6.y; a2.z += v6.z; a2.w += v6.w;
                a3.x += v7.x; a3.y += v7.y; a3.z += v7.z; a3.w += v7.w;
            }
            for (; j < m; j++) {
                int s = __shfl_sync(0xffffffffu, idx, j);
                float4 v = X[s * 32 + lane];
                a0.x += v.x; a0.y += v.y; a0.z += v.z; a0.w += v.w;
            }
        }
        float4 r = ((const float4*)xr)[gw * 32 + lane];
        float4 o;
        o.x = (a0.x + a1.x + a2.x + a3.x) * inv + r.x;
        o.y = (a0.y + a1.y + a2.y + a3.y) * inv + r.y;
        o.z = (a0.z + a1.z + a2.z + a3.z) * inv + r.z;
        o.w = (a0.w + a1.w + a2.w + a3.w) * inv + r.w;
        if (RELU) {
            o.x = fmaxf(o.x, 0.f); o.y = fmaxf(o.y, 0.f);
            o.z = fmaxf(o.z, 0.f); o.w = fmaxf(o.w, 0.f);
        }
        ((float4*)out)[gw * 32 + lane] = o;
    } else {  // DOUT == 64, float2 per lane
        const float2* X = (const float2*)xl;
        float2 a0 = {0,0}, a1 = {0,0}, a2 = {0,0}, a3 = {0,0};
        for (int base = beg; base < end; base += 32) {
            int m = end - base; if (m > 32) m = 32;
            int p = base + lane; if (p >= end) p = end - 1;
            int idx = g_col[p];
            int j = 0;
            for (; j + 8 <= m; j += 8) {
                int s0 = __shfl_sync(0xffffffffu, idx, j + 0);
                int s1 = __shfl_sync(0xffffffffu, idx, j + 1);
                int s2 = __shfl_sync(0xffffffffu, idx, j + 2);
                int s3 = __shfl_sync(0xffffffffu, idx, j + 3);
                int s4 = __shfl_sync(0xffffffffu, idx, j + 4);
                int s5 = __shfl_sync(0xffffffffu, idx, j + 5);
                int s6 = __shfl_sync(0xffffffffu, idx, j + 6);
                int s7 = __shfl_sync(0xffffffffu, idx, j + 7);
                float2 v0 = X[s0 * 32 + lane];
                float2 v1 = X[s1 * 32 + lane];
                float2 v2 = X[s2 * 32 + lane];
                float2 v3 = X[s3 * 32 + lane];
                float2 v4 = X[s4 * 32 + lane];
                float2 v5 = X[s5 * 32 + lane];
                float2 v6 = X[s6 * 32 + lane];
                float2 v7 = X[s7 * 32 + lane];
                a0.x += v0.x; a0.y += v0.y;
                a1.x += v1.x; a1.y += v1.y;
                a2.x += v2.x; a2.y += v2.y;
                a3.x += v3.x; a3.y += v3.y;
                a0.x += v4.x; a0.y += v4.y;
                a1.x += v5.x; a1.y += v5.y;
                a2.x += v6.x; a2.y += v6.y;
                a3.x += v7.x; a3.y += v7.y;
            }
            for (; j < m; j++) {
                int s = __shfl_sync(0xffffffffu, idx, j);
                float2 v = X[s * 32 + lane];
                a0.x += v.x; a0.y += v.y;
            }
        }
        float2 r = ((const float2*)xr)[gw * 32 + lane];
        float2 o;
        o.x = (a0.x + a1.x + a2.x + a3.x) * inv + r.x;
        o.y = (a0.y + a1.y + a2.y + a3.y) * inv + r.y;
        if (RELU) { o.x = fmaxf(o.x, 0.f); o.y = fmaxf(o.y, 0.f); }
        ((float2*)out)[gw * 32 + lane] = o;
    }
}

// ============================================================
// Launch
// ============================================================
extern "C" void kernel_launch(void* const* d_in, const int* in_sizes, int n_in,
                              void* d_out, int out_size)
{
    const float* x   = (const float*)d_in[0];
    const int*   ei  = (const int*)d_in[1];
    const float* Wl0 = (const float*)d_in[2];
    const float* Wr0 = (const float*)d_in[3];
    const float* b0  = (const float*)d_in[4];
    const float* Wl1 = (const float*)d_in[5];
    const float* Wr1 = (const float*)d_in[6];
    const float* b1  = (const float*)d_in[7];
    const float* Wl2 = (const float*)d_in[8];
    const float* Wr2 = (const float*)d_in[9];
    const float* b2  = (const float*)d_in[10];

    const int n = in_sizes[0] / 128;
    const int e = in_sizes[1] / 2;
    const int* src = ei;
    const int* dst = ei + e;

    void *pxl, *pxr, *ph, *ph2, *pdeg;
    cudaGetSymbolAddress(&pxl, g_xl);
    cudaGetSymbolAddress(&pxr, g_xr);
    cudaGetSymbolAddress(&ph,  g_h);
    cudaGetSymbolAddress(&ph2, g_h2);
    cudaGetSymbolAddress(&pdeg, g_deg);
    float* f_xl = (float*)pxl;
    float* f_xr = (float*)pxr;
    float* f_h  = (float*)ph;
    float* f_h2 = (float*)ph2;

    // smem sizes for the full-K GEMM
    constexpr int SM128 = (64 * 132 + 128 * 132) * 4;  // 101376 B
    constexpr int SM64  = (64 * 132 + 128 * 68) * 4;   //  68608 B
    static bool attr_set = false;
    if (!attr_set) {
        cudaFuncSetAttribute(gemm_fullk<128>, cudaFuncAttributeMaxDynamicSharedMemorySize, SM128);
        cudaFuncSetAttribute(gemm_fullk<64>,  cudaFuncAttributeMaxDynamicSharedMemorySize, SM64);
        attr_set = true;
    }

    // CSR build (per-launch)
    cudaMemsetAsync(pdeg, 0, (size_t)n * sizeof(int));
    hist_k<<<(e + 255) / 256, 256>>>(dst, e);
    scan_k<<<1, 1024>>>(n);
    scatter_k<<<(e + 255) / 256, 256>>>(src, dst, e);

    dim3 gg((n + 63) / 64, 2);
    int agg_blocks = (n + 7) / 8;  // 8 warps/block, one warp per node

    // Layer 0: h = relu(mean_agg(x@Wl0) + x@Wr0 + b0)
    gemm_fullk<128><<<gg, 256, SM128>>>(x, Wl0, Wr0, b0, f_xl, f_xr, n);
    agg_ep<128, true><<<agg_blocks, 256>>>(f_xl, f_xr, f_h, n);

    // Layer 1
    gemm_fullk<128><<<gg, 256, SM128>>>(f_h, Wl1, Wr1, b1, f_xl, f_xr, n);
    agg_ep<128, true><<<agg_blocks, 256>>>(f_xl, f_xr, f_h2, n);

    // Layer 2 (DOUT=64, no relu) -> d_out
    gemm_fullk<64><<<gg, 256, SM64>>>(f_h2, Wl2, Wr2, b2, f_xl, f_xr, n);
    agg_ep<64, false><<<agg_blocks, 256>>>(f_xl, f_xr, (float*)d_out, n);
}

// round 4
// speedup vs baseline: 1.0579x; 1.0579x over previous
#include <cuda_runtime.h>
#include <cstdint>
#include <cstddef>

// Problem constants (match reference)
#define NMAX 100000
#define EMAX 1600000
#define K_DIM 128

// ---- Scratch (device globals; no allocations allowed) ----
__device__ int   g_deg[NMAX];
__device__ int   g_rowptr[NMAX + 1];
__device__ int   g_fill[NMAX];
__device__ int   g_col[EMAX];
__device__ float g_xl[(size_t)NMAX * 128];   // aggregated-path transform
__device__ float g_xr[(size_t)NMAX * 128];   // self-path transform (+bias)
__device__ float g_h[(size_t)NMAX * 128];    // layer-0 output
__device__ float g_h2[(size_t)NMAX * 128];   // layer-1 output

// ============================================================
// CSR build (counting sort by dst), rebuilt every launch
// ============================================================
__global__ void hist_k(const int* __restrict__ dst, int e) {
    int i = blockIdx.x * blockDim.x + threadIdx.x;
    if (i < e) atomicAdd(&g_deg[dst[i]], 1);
}

__global__ __launch_bounds__(1024) void scan_k(int n) {
    __shared__ int part[1024];
    int tid = threadIdx.x;
    int chunk = (n + 1023) >> 10;
    int beg = tid * chunk;
    int end = min(beg + chunk, n);
    int s = 0;
    for (int i = beg; i < end; i++) s += g_deg[i];
    part[tid] = s;
    __syncthreads();
    for (int off = 1; off < 1024; off <<= 1) {
        int v = (tid >= off) ? part[tid - off] : 0;
        __syncthreads();
        part[tid] += v;
        __syncthreads();
    }
    int base = part[tid] - s;  // exclusive prefix
    for (int i = beg; i < end; i++) {
        g_rowptr[i] = base;
        g_fill[i]   = base;
        base += g_deg[i];
    }
    if (tid == 1023) g_rowptr[n] = part[1023];
}

__global__ void scatter_k(const int* __restrict__ src, const int* __restrict__ dst, int e) {
    int i = blockIdx.x * blockDim.x + threadIdx.x;
    if (i < e) {
        int p = atomicAdd(&g_fill[dst[i]], 1);
        g_col[p] = src[i];
    }
}

// ============================================================
// tf32 helpers
// ============================================================
__device__ __forceinline__ uint32_t f2tf(float x) {
    uint32_t u;
    asm("cvt.rna.tf32.f32 %0, %1;" : "=r"(u) : "f"(x));
    return u;
}

__device__ __forceinline__ void mma_tf32(
    float c[4], uint32_t a0, uint32_t a1, uint32_t a2, uint32_t a3,
    uint32_t b0, uint32_t b1)
{
    asm volatile(
        "mma.sync.aligned.m16n8k8.row.col.f32.tf32.tf32.f32 "
        "{%0,%1,%2,%3}, {%4,%5,%6,%7}, {%8,%9}, {%0,%1,%2,%3};"
        : "+f"(c[0]), "+f"(c[1]), "+f"(c[2]), "+f"(c[3])
        : "r"(a0), "r"(a1), "r"(a2), "r"(a3), "r"(b0), "r"(b1));
}

// ============================================================
// Fused dual GEMM, software-pipelined (tf32 tensor cores):
//   Cl = A @ Wl ; Cr = A @ Wr + bias  — ONE block does both for its rows.
// A: [n,128] row-major staged ONCE (BM=128 x K=128 in smem).
// W streamed in BK=32 k-chunks, double-buffered:
//   prefetch chunk c+1 (global->regs) ; mma chunk c ; STS c+1 ; sync.
// 8 warps: warp w handles rows [w*16, w*16+16), all DOUT columns.
// ============================================================
template <int DOUT>
__global__ __launch_bounds__(256) void gemm_dual(
    const float* __restrict__ A,
    const float* __restrict__ Wl, const float* __restrict__ Wr,
    const float* __restrict__ bias,
    float* __restrict__ Cl, float* __restrict__ Cr, int n)
{
    constexpr int BM = 128, BK = 32;
    constexpr int AS_STRIDE = K_DIM + 4;       // 132
    constexpr int BS_STRIDE = DOUT + 4;
    constexpr int NF = DOUT / 8;               // n-frags per warp
    constexpr int WV = (BK * DOUT) / (4 * 256);  // float4 per thread per W chunk (4 or 2)
    constexpr int NCH = K_DIM / BK;            // 4 chunks per W matrix

    extern __shared__ uint32_t smraw[];
    uint32_t (*As)[AS_STRIDE] = (uint32_t(*)[AS_STRIDE])smraw;                 // [128][132]
    uint32_t (*Bs)[BK][BS_STRIDE] =
        (uint32_t(*)[BK][BS_STRIDE])(smraw + BM * AS_STRIDE);                  // [2][32][DOUT+4]

    const int tid  = threadIdx.x;
    const int row0 = blockIdx.x * BM;

    // ---- stage A: BM x K (16 float4/thread), once ----
#pragma unroll
    for (int v = 0; v < (BM * K_DIM) / (4 * 256); v++) {
        int idx = tid + v * 256;
        int r   = idx >> 5;
        int kq  = (idx & 31) * 4;
        float4 av = make_float4(0.f, 0.f, 0.f, 0.f);
        int gr = row0 + r;
        if (gr < n) av = *(const float4*)(A + (size_t)gr * K_DIM + kq);
        uint4 uv;
        uv.x = f2tf(av.x); uv.y = f2tf(av.y);
        uv.z = f2tf(av.z); uv.w = f2tf(av.w);
        *(uint4*)&As[r][kq] = uv;
    }

    // W chunk staging helpers
    const int wkk = tid / (DOUT / 4);          // k row within chunk (per float4 slot 0)
    const int wc4 = (tid % (DOUT / 4)) * 4;    // col offset
    constexpr int KROWS_PER_PASS = 256 / (DOUT / 4);  // k rows covered per 256-thread pass

    float4 wreg[WV];
    // prefetch chunk 0 of Wl
#pragma unroll
    for (int v = 0; v < WV; v++)
        wreg[v] = *(const float4*)(Wl + (size_t)(wkk + v * KROWS_PER_PASS) * DOUT + wc4);
#pragma unroll
    for (int v = 0; v < WV; v++) {
        uint4 uv;
        uv.x = f2tf(wreg[v].x); uv.y = f2tf(wreg[v].y);
        uv.z = f2tf(wreg[v].z); uv.w = f2tf(wreg[v].w);
        *(uint4*)&Bs[0][wkk + v * KROWS_PER_PASS][wc4] = uv;
    }
    __syncthreads();

    const int warp = tid >> 5;
    const int lane = tid & 31;
    const int g    = lane >> 2;
    const int tig  = lane & 3;
    const int wrow = warp * 16;

    float acc[NF][4];
#pragma unroll
    for (int f = 0; f < NF; f++)
#pragma unroll
        for (int j = 0; j < 4; j++) acc[f][j] = 0.f;

    int buf = 0;
    for (int c = 0; c < 2 * NCH; c++) {
        // ---- prefetch next chunk into registers (latency hidden by mma) ----
        if (c + 1 < 2 * NCH) {
            const float* Wn = (c + 1 < NCH) ? Wl : Wr;
            int cc = (c + 1) & (NCH - 1);
#pragma unroll
            for (int v = 0; v < WV; v++)
                wreg[v] = *(const float4*)(Wn + (size_t)(cc * BK + wkk + v * KROWS_PER_PASS) * DOUT + wc4);
        }

        // ---- mma over current chunk ----
        const int kbase = (c & (NCH - 1)) * BK;
#pragma unroll
        for (int ks = 0; ks < BK / 8; ks++) {
            const int kb = kbase + ks * 8;
            const int lb = ks * 8;
            uint32_t a0 = As[wrow + g][kb + tig];
            uint32_t a1 = As[wrow + g + 8][kb + tig];
            uint32_t a2 = As[wrow + g][kb + tig + 4];
            uint32_t a3 = As[wrow + g + 8][kb + tig + 4];
#pragma unroll
            for (int f = 0; f < NF; f++) {
                int col = f * 8 + g;
                uint32_t b0 = Bs[buf][lb + tig][col];
                uint32_t b1 = Bs[buf][lb + tig + 4][col];
                mma_tf32(acc[f], a0, a1, a2, a3, b0, b1);
            }
        }

        // ---- end of Wl: write Cl, reset acc ----
        if (c == NCH - 1) {
            const int r_lo = row0 + wrow + g;
            const int r_hi = r_lo + 8;
#pragma unroll
            for (int f = 0; f < NF; f++) {
                int col = f * 8 + 2 * tig;
                if (r_lo < n)
                    *(float2*)(Cl + (size_t)r_lo * DOUT + col) = make_float2(acc[f][0], acc[f][1]);
                if (r_hi < n)
                    *(float2*)(Cl + (size_t)r_hi * DOUT + col) = make_float2(acc[f][2], acc[f][3]);
#pragma unroll
                for (int j = 0; j < 4; j++) acc[f][j] = 0.f;
            }
        }

        // ---- commit prefetched chunk to the other buffer ----
        if (c + 1 < 2 * NCH) {
#pragma unroll
            for (int v = 0; v < WV; v++) {
                uint4 uv;
                uv.x = f2tf(wreg[v].x); uv.y = f2tf(wreg[v].y);
                uv.z = f2tf(wreg[v].z); uv.w = f2tf(wreg[v].w);
                *(uint4*)&Bs[buf ^ 1][wkk + v * KROWS_PER_PASS][wc4] = uv;
            }
            __syncthreads();
            buf ^= 1;
        }
    }

    // ---- final epilogue: Cr with bias ----
    const int r_lo = row0 + wrow + g;
    const int r_hi = r_lo + 8;
#pragma unroll
    for (int f = 0; f < NF; f++) {
        int col = f * 8 + 2 * tig;
        float bv0 = bias[col];
        float bv1 = bias[col + 1];
        if (r_lo < n)
            *(float2*)(Cr + (size_t)r_lo * DOUT + col) = make_float2(acc[f][0] + bv0, acc[f][1] + bv1);
        if (r_hi < n)
            *(float2*)(Cr + (size_t)r_hi * DOUT + col) = make_float2(acc[f][2] + bv0, acc[f][3] + bv1);
    }
}

// ============================================================
// Aggregation + epilogue: out[n] = relu?( mean_{s in N(n)} xl[s] + xr[n] )
// One warp per destination node; coalesced index fetch + shfl broadcast;
// 8 row-gathers in flight.
// ============================================================
template <int DOUT, bool RELU>
__global__ __launch_bounds__(256) void agg_ep(
    const float* __restrict__ xl, const float* __restrict__ xr,
    float* __restrict__ out, int n)
{
    int gw   = (blockIdx.x * blockDim.x + threadIdx.x) >> 5;
    int lane = threadIdx.x & 31;
    if (gw >= n) return;

    int beg = g_rowptr[gw];
    int end = g_rowptr[gw + 1];
    float inv = 1.f / fmaxf((float)(end - beg), 1.f);

    if (DOUT == 128) {
        const float4* X = (const float4*)xl;
        float4 a0 = {0,0,0,0}, a1 = {0,0,0,0}, a2 = {0,0,0,0}, a3 = {0,0,0,0};
        for (int base = beg; base < end; base += 32) {
            int m = end - base; if (m > 32) m = 32;
            int p = base + lane; if (p >= end) p = end - 1;
            int idx = g_col[p];
            int j = 0;
            for (; j + 8 <= m; j += 8) {
                int s0 = __shfl_sync(0xffffffffu, idx, j + 0);
                int s1 = __shfl_sync(0xffffffffu, idx, j + 1);
                int s2 = __shfl_sync(0xffffffffu, idx, j + 2);
                int s3 = __shfl_sync(0xffffffffu, idx, j + 3);
                int s4 = __shfl_sync(0xffffffffu, idx, j + 4);
                int s5 = __shfl_sync(0xffffffffu, idx, j + 5);
                int s6 = __shfl_sync(0xffffffffu, idx, j + 6);
                int s7 = __shfl_sync(0xffffffffu, idx, j + 7);
                float4 v0 = X[s0 * 32 + lane];
                float4 v1 = X[s1 * 32 + lane];
                float4 v2 = X[s2 * 32 + lane];
                float4 v3 = X[s3 * 32 + lane];
                float4 v4 = X[s4 * 32 + lane];
                float4 v5 = X[s5 * 32 + lane];
                float4 v6 = X[s6 * 32 + lane];
                float4 v7 = X[s7 * 32 + lane];
                a0.x += v0.x; a0.y += v0.y; a0.z += v0.z; a0.w += v0.w;
                a1.x += v1.x; a1.y += v1.y; a1.z += v1.z; a1.w += v1.w;
                a2.x += v2.x; a2.y += v2.y; a2.z += v2.z; a2.w += v2.w;
                a3.x += v3.x; a3.y += v3.y; a3.z += v3.z; a3.w += v3.w;
                a0.x += v4.x; a0.y += v4.y; a0.z += v4.z; a0.w += v4.w;
                a1.x += v5.x; a1.y += v5.y; a1.z += v5.z; a1.w += v5.w;
                a2.x += v6.x; a2.y += v6.y; a2.z += v6.z; a2.w += v6.w;
                a3.x += v7.x; a3.y += v7.y; a3.z += v7.z; a3.w += v7.w;
            }
            for (; j < m; j++) {
                int s = __shfl_sync(0xffffffffu, idx, j);
                float4 v = X[s * 32 + lane];
                a0.x += v.x; a0.y += v.y; a0.z += v.z; a0.w += v.w;
            }
        }
        float4 r = ((const float4*)xr)[gw * 32 + lane];
        float4 o;
        o.x = (a0.x + a1.x + a2.x + a3.x) * inv + r.x;
        o.y = (a0.y + a1.y + a2.y + a3.y) * inv + r.y;
        o.z = (a0.z + a1.z + a2.z + a3.z) * inv + r.z;
        o.w = (a0.w + a1.w + a2.w + a3.w) * inv + r.w;
        if (RELU) {
            o.x = fmaxf(o.x, 0.f); o.y = fmaxf(o.y, 0.f);
            o.z = fmaxf(o.z, 0.f); o.w = fmaxf(o.w, 0.f);
        }
        ((float4*)out)[gw * 32 + lane] = o;
    } else {  // DOUT == 64, float2 per lane
        const float2* X = (const float2*)xl;
        float2 a0 = {0,0}, a1 = {0,0}, a2 = {0,0}, a3 = {0,0};
        for (int base = beg; base < end; base += 32) {
            int m = end - base; if (m > 32) m = 32;
            int p = base + lane; if (p >= end) p = end - 1;
            int idx = g_col[p];
            int j = 0;
            for (; j + 8 <= m; j += 8) {
                int s0 = __shfl_sync(0xffffffffu, idx, j + 0);
                int s1 = __shfl_sync(0xffffffffu, idx, j + 1);
                int s2 = __shfl_sync(0xffffffffu, idx, j + 2);
                int s3 = __shfl_sync(0xffffffffu, idx, j + 3);
                int s4 = __shfl_sync(0xffffffffu, idx, j + 4);
                int s5 = __shfl_sync(0xffffffffu, idx, j + 5);
                int s6 = __shfl_sync(0xffffffffu, idx, j + 6);
                int s7 = __shfl_sync(0xffffffffu, idx, j + 7);
                float2 v0 = X[s0 * 32 + lane];
                float2 v1 = X[s1 * 32 + lane];
                float2 v2 = X[s2 * 32 + lane];
                float2 v3 = X[s3 * 32 + lane];
                float2 v4 = X[s4 * 32 + lane];
                float2 v5 = X[s5 * 32 + lane];
                float2 v6 = X[s6 * 32 + lane];
                float2 v7 = X[s7 * 32 + lane];
                a0.x += v0.x; a0.y += v0.y;
                a1.x += v1.x; a1.y += v1.y;
                a2.x += v2.x; a2.y += v2.y;
                a3.x += v3.x; a3.y += v3.y;
                a0.x += v4.x; a0.y += v4.y;
                a1.x += v5.x; a1.y += v5.y;
                a2.x += v6.x; a2.y += v6.y;
                a3.x += v7.x; a3.y += v7.y;
            }
            for (; j < m; j++) {
                int s = __shfl_sync(0xffffffffu, idx, j);
                float2 v = X[s * 32 + lane];
                a0.x += v.x; a0.y += v.y;
            }
        }
        float2 r = ((const float2*)xr)[gw * 32 + lane];
        float2 o;
        o.x = (a0.x + a1.x + a2.x + a3.x) * inv + r.x;
        o.y = (a0.y + a1.y + a2.y + a3.y) * inv + r.y;
        if (RELU) { o.x = fmaxf(o.x, 0.f); o.y = fmaxf(o.y, 0.f); }
        ((float2*)out)[gw * 32 + lane] = o;
    }
}

// ============================================================
// Launch
// ============================================================
extern "C" void kernel_launch(void* const* d_in, const int* in_sizes, int n_in,
                              void* d_out, int out_size)
{
    const float* x   = (const float*)d_in[0];
    const int*   ei  = (const int*)d_in[1];
    const float* Wl0 = (const float*)d_in[2];
    const float* Wr0 = (const float*)d_in[3];
    const float* b0  = (const float*)d_in[4];
    const float* Wl1 = (const float*)d_in[5];
    const float* Wr1 = (const float*)d_in[6];
    const float* b1  = (const float*)d_in[7];
    const float* Wl2 = (const float*)d_in[8];
    const float* Wr2 = (const float*)d_in[9];
    const float* b2  = (const float*)d_in[10];

    const int n = in_sizes[0] / 128;
    const int e = in_sizes[1] / 2;
    const int* src = ei;
    const int* dst = ei + e;

    void *pxl, *pxr, *ph, *ph2, *pdeg;
    cudaGetSymbolAddress(&pxl, g_xl);
    cudaGetSymbolAddress(&pxr, g_xr);
    cudaGetSymbolAddress(&ph,  g_h);
    cudaGetSymbolAddress(&ph2, g_h2);
    cudaGetSymbolAddress(&pdeg, g_deg);
    float* f_xl = (float*)pxl;
    float* f_xr = (float*)pxr;
    float* f_h  = (float*)ph;
    float* f_h2 = (float*)ph2;

    // smem: A[128][132] + 2 x Bs[32][DOUT+4]
    constexpr int SM128 = (128 * 132 + 2 * 32 * 132) * 4;  // 101376 B
    constexpr int SM64  = (128 * 132 + 2 * 32 * 68) * 4;   //  84992 B
    static bool attr_set = false;
    if (!attr_set) {
        cudaFuncSetAttribute(gemm_dual<128>, cudaFuncAttributeMaxDynamicSharedMemorySize, SM128);
        cudaFuncSetAttribute(gemm_dual<64>,  cudaFuncAttributeMaxDynamicSharedMemorySize, SM64);
        attr_set = true;
    }

    // CSR build (per-launch)
    cudaMemsetAsync(pdeg, 0, (size_t)n * sizeof(int));
    hist_k<<<(e + 255) / 256, 256>>>(dst, e);
    scan_k<<<1, 1024>>>(n);
    scatter_k<<<(e + 255) / 256, 256>>>(src, dst, e);

    const int gemm_blocks = (n + 127) / 128;
    const int agg_blocks  = (n + 7) / 8;  // 8 warps/block, one warp per node

    // Layer 0: h = relu(mean_agg(x@Wl0) + x@Wr0 + b0)
    gemm_dual<128><<<gemm_blocks, 256, SM128>>>(x, Wl0, Wr0, b0, f_xl, f_xr, n);
    agg_ep<128, true><<<agg_blocks, 256>>>(f_xl, f_xr, f_h, n);

    // Layer 1
    gemm_dual<128><<<gemm_blocks, 256, SM128>>>(f_h, Wl1, Wr1, b1, f_xl, f_xr, n);
    agg_ep<128, true><<<agg_blocks, 256>>>(f_xl, f_xr, f_h2, n);

    // Layer 2 (DOUT=64, no relu) -> d_out
    gemm_dual<64><<<gemm_blocks, 256, SM64>>>(f_h2, Wl2, Wr2, b2, f_xl, f_xr, n);
    agg_ep<64, false><<<agg_blocks, 256>>>(f_xl, f_xr, (float*)d_out, n);
}